// round 14
// baseline (speedup 1.0000x reference)
#include <cuda_runtime.h>
#include <cstdint>
#include <math.h>

#define BB 8
#define NN 4096
#define KK 16

typedef unsigned long long ull;
#define FMA2(d,a,b) asm("fma.rn.f32x2 %0, %1, %2, %0;" : "+l"(d) : "l"(a), "l"(b))

__device__ int    g_idx[BB*NN*KK];
__device__ float  g_G[BB*NN*64];
__device__ float  g_H[BB*NN*64];
__device__ float  g_y1[(size_t)BB*NN*KK*64];
__device__ float  g_mx[(size_t)BB*NN*128];
__device__ float  g_mn[(size_t)BB*NN*128];
__device__ double g_sum0[64], g_sq0[64], g_sum1[64], g_sq1[64], g_sum2[128], g_sq2[128];

__device__ __forceinline__ int swi(int col, int c) {
    return (col << 6) + ((((c >> 2) ^ col) & 15) << 2) + (c & 3);
}
__device__ __forceinline__ int swi4(int col, int chunk) {
    return (col << 6) + (((chunk ^ col) & 15) << 2);
}
__device__ __forceinline__ float lo32(ull u) { return __uint_as_float((unsigned)u); }
__device__ __forceinline__ float hi32(ull u) { return __uint_as_float((unsigned)(u >> 32)); }
__device__ __forceinline__ unsigned int shaddr(const void* p) {
    return (unsigned int)__cvta_generic_to_shared(p);
}
__device__ __forceinline__ void cp_async16(unsigned int s, const void* g) {
    asm volatile("cp.async.cg.shared.global [%0], [%1], 16;" :: "r"(s), "l"(g) : "memory");
}
__device__ __forceinline__ void cp_commit() {
    asm volatile("cp.async.commit_group;" ::: "memory");
}
__device__ __forceinline__ void cp_wait0() {
    asm volatile("cp.async.wait_group 0;" ::: "memory");
}

// ---------------- KNN: full 4096-ref scan per query (no chunking, no merge) ----------------
__global__ __launch_bounds__(128) void knn_kernel(const float* __restrict__ q,
                                                  const float* __restrict__ r) {
    if (blockIdx.x == 0 && blockIdx.y == 0) {
        int i = threadIdx.x;
        if (i < 64) { g_sum0[i]=0.0; g_sq0[i]=0.0; g_sum1[i]=0.0; g_sq1[i]=0.0; }
        if (i < 128){ g_sum2[i]=0.0; g_sq2[i]=0.0; }
    }
    __shared__ float4 refs[512];
    int b = blockIdx.y;
    int n = blockIdx.x * 128 + threadIdx.x;
    const float* qb = q + b*3*NN;
    float qx = qb[n], qy = qb[NN+n], qz = qb[2*NN+n];
    float q2 = qx*qx + qy*qy + qz*qz;
    float dist[16]; int ind[16];
#pragma unroll
    for (int i = 0; i < 16; i++) { dist[i] = 3.4e38f; ind[i] = 0; }
    const float* rb = r + b*3*NN;
    for (int t = 0; t < NN; t += 512) {
        __syncthreads();
        for (int j = threadIdx.x; j < 512; j += 128) {
            float rx = rb[t+j], ry = rb[NN+t+j], rz = rb[2*NN+t+j];
            refs[j] = make_float4(rx, ry, rz, rx*rx + ry*ry + rz*rz);
        }
        __syncthreads();
#pragma unroll 2
        for (int j = 0; j < 512; j++) {
            float4 rv = refs[j];
            float dot = fmaf(qx, rv.x, fmaf(qy, rv.y, qz*rv.z));
            float d = fmaf(-2.f, dot, q2 + rv.w);
            if (d < dist[15]) {
                float dd = d; int mi = t + j;
#pragma unroll
                for (int s = 0; s < 16; s++) {
                    if (dd < dist[s]) {
                        float td = dist[s]; dist[s] = dd; dd = td;
                        int   ti = ind[s];  ind[s]  = mi; mi = ti;
                    }
                }
            }
        }
    }
    int base = (b*NN + n)*16;
#pragma unroll
    for (int i = 0; i < 16; i++) g_idx[base+i] = ind[i];
}

// ---------------- G/H GEMM (512 blocks) ----------------
__global__ __launch_bounds__(256) void gh_kernel(const float* __restrict__ pos1,
                                                 const float* __restrict__ pos2,
                                                 const float* __restrict__ f1,
                                                 const float* __restrict__ f2,
                                                 const float* __restrict__ W0) {
    __shared__ float Wt[67][32];
    __shared__ float Xs[8][256];
    int tid = threadIdx.x;
    int g = blockIdx.x;
    int isH = g >> 8;
    int oh  = (g >> 7) & 1;
    int bt  = g & 127;
    int b = bt >> 4, m0 = (bt & 15) * 256;
    const float* pos  = isH ? pos1 : pos2;
    const float* feat = isH ? f1   : f2;
    for (int i = tid; i < 32*67; i += 256) {
        int o = i & 31, c = i >> 5;
        int gc = (c < 3) ? c : (isH ? c + 64 : c);
        Wt[c][o] = W0[(oh*32 + o)*131 + gc];
    }
    __syncthreads();
    int m = m0 + tid;
    const float* pp = pos + b*3*NN;
    float p0 = pp[m], p1 = pp[NN+m], p2 = pp[2*NN+m];
    if (isH) { p0 = -p0; p1 = -p1; p2 = -p2; }
    float acc[32];
#pragma unroll
    for (int o = 0; o < 32; o++)
        acc[o] = fmaf(Wt[0][o], p0, fmaf(Wt[1][o], p1, Wt[2][o]*p2));
    const float* fb = feat + (size_t)b*64*NN + m0;
    for (int cc = 0; cc < 64; cc += 8) {
        __syncthreads();
        for (int i = tid; i < 2048; i += 256) {
            int r = i >> 8, mm = i & 255;
            Xs[r][mm] = fb[(size_t)(cc + r)*NN + mm];
        }
        __syncthreads();
#pragma unroll
        for (int r = 0; r < 8; r++) {
            float x = Xs[r][tid];
            const float* w = &Wt[3 + cc + r][0];
#pragma unroll
            for (int o4 = 0; o4 < 32; o4 += 4) {
                float4 wv = *(const float4*)(w + o4);
                acc[o4+0] = fmaf(wv.x, x, acc[o4+0]);
                acc[o4+1] = fmaf(wv.y, x, acc[o4+1]);
                acc[o4+2] = fmaf(wv.z, x, acc[o4+2]);
                acc[o4+3] = fmaf(wv.w, x, acc[o4+3]);
            }
        }
    }
    float* outp = (isH ? g_H : g_G) + ((size_t)((b<<12) + m) << 6) + oh*32;
#pragma unroll
    for (int o4 = 0; o4 < 32; o4 += 4)
        *(float4*)(outp + o4) = make_float4(acc[o4], acc[o4+1], acc[o4+2], acc[o4+3]);
}

__global__ void stats0_kernel() {
    __shared__ float bsum[64], bsq[64];
    int tid = threadIdx.x;
    if (tid < 64) { bsum[tid] = 0.f; bsq[tid] = 0.f; }
    __syncthreads();
    int warp = tid >> 5, lane = tid & 31;
    int c4 = lane & 15, r2 = lane >> 4;
    int p0 = blockIdx.x*16 + warp*2;
    int p1 = p0 + 1;
    int b = p0 >> 12;
    int mk = g_idx[p0*16 + lane];
    float4 hA = *(const float4*)(g_H + (size_t)p0*64 + c4*4);
    float4 hB = *(const float4*)(g_H + (size_t)p1*64 + c4*4);
    float4 s = make_float4(0,0,0,0), qq = make_float4(0,0,0,0);
#pragma unroll
    for (int st = 0; st < 16; st++) {
        int row = 2*st + r2;
        int m = __shfl_sync(0xffffffffu, mk, row);
        float4 g4 = *(const float4*)(g_G + ((size_t)((b<<12) + m) << 6) + (c4<<2));
        float4 h = (row < 16) ? hA : hB;
        float vx = g4.x + h.x, vy = g4.y + h.y, vz = g4.z + h.z, vw = g4.w + h.w;
        s.x += vx; s.y += vy; s.z += vz; s.w += vw;
        qq.x = fmaf(vx, vx, qq.x); qq.y = fmaf(vy, vy, qq.y);
        qq.z = fmaf(vz, vz, qq.z); qq.w = fmaf(vw, vw, qq.w);
    }
    s.x += __shfl_xor_sync(0xffffffffu, s.x, 16);
    s.y += __shfl_xor_sync(0xffffffffu, s.y, 16);
    s.z += __shfl_xor_sync(0xffffffffu, s.z, 16);
    s.w += __shfl_xor_sync(0xffffffffu, s.w, 16);
    qq.x += __shfl_xor_sync(0xffffffffu, qq.x, 16);
    qq.y += __shfl_xor_sync(0xffffffffu, qq.y, 16);
    qq.z += __shfl_xor_sync(0xffffffffu, qq.z, 16);
    qq.w += __shfl_xor_sync(0xffffffffu, qq.w, 16);
    if (lane < 16) {
        atomicAdd(&bsum[c4*4+0], s.x); atomicAdd(&bsum[c4*4+1], s.y);
        atomicAdd(&bsum[c4*4+2], s.z); atomicAdd(&bsum[c4*4+3], s.w);
        atomicAdd(&bsq[c4*4+0], qq.x); atomicAdd(&bsq[c4*4+1], qq.y);
        atomicAdd(&bsq[c4*4+2], qq.z); atomicAdd(&bsq[c4*4+3], qq.w);
    }
    __syncthreads();
    if (tid < 64) { atomicAdd(&g_sum0[tid], (double)bsum[tid]); atomicAdd(&g_sq0[tid], (double)bsq[tid]); }
}

// ---------------- layer1: persistent, cp.async double-buffered ----------------
__global__ __launch_bounds__(256,2) void layer1_kernel(const float* __restrict__ W1,
                                                       const float* __restrict__ gg0,
                                                       const float* __restrict__ bb0) {
    extern __shared__ float sm[];
    float* Ws   = sm;
    float* xs   = sm + 4096;
    float* hs   = sm + 4096 + 16384;
    float* s0s  = hs + 1024;
    float* t0s  = s0s + 64;
    float* bsum = t0s + 64;
    float* bsq  = bsum + 64;
    int*   idxb = (int*)(bsq + 64);
    int tid = threadIdx.x;
    for (int i = tid; i < 4096; i += 256) { int o=i>>6, c=i&63; Ws[swi(o,c)] = W1[i]; }
    if (tid < 64) {
        const double cnt = (double)BB*NN*KK;
        double mean = g_sum0[tid] / cnt;
        double var  = g_sq0[tid] / cnt - mean*mean;
        float sv = gg0[tid] * rsqrtf((float)var + 1e-5f);
        s0s[tid] = sv;
        t0s[tid] = bb0[tid] - (float)mean * sv;
        bsum[tid] = 0.f; bsq[tid] = 0.f;
    }
    int GRID = gridDim.x;
    int T0 = blockIdx.x;
    if (tid < 128) {
        idxb[tid] = g_idx[T0*128 + tid];
        if (T0 + GRID < 4096) idxb[128 + tid] = g_idx[(T0+GRID)*128 + tid];
        cp_async16(shaddr(hs + tid*4), g_H + (size_t)T0*512 + tid*4);
    }
    __syncthreads();
    {
        int bb = T0 >> 9;
#pragma unroll
        for (int k = 0; k < 8; k++) {
            int i = tid + k*256, col = i>>4, c4 = i&15;
            int m = idxb[col];
            cp_async16(shaddr(xs + swi4(col,c4)),
                       g_G + (((size_t)(bb<<12) + m)<<6) + (c4<<2));
        }
    }
    cp_commit();
    int p = 0, t = 0;
    for (int T = T0; T < 4096; T += GRID, t++) {
        int pbase = T*8;
        float* xsp = xs + p*8192;
        float* hsp = hs + p*512;
        cp_wait0(); __syncthreads();
        const float4* s0v = (const float4*)s0s;
        const float4* t0v = (const float4*)t0s;
#pragma unroll
        for (int k = 0; k < 8; k++) {
            int i = tid + k*256, col = i>>4, c4 = i&15;
            float4 g4 = *(float4*)(xsp + swi4(col,c4));
            float4 h4 = *(float4*)(hsp + (col>>4)*64 + (c4<<2));
            float4 sv = s0v[c4], tv = t0v[c4], v;
            v.x = fmaxf(fmaf(sv.x, g4.x+h4.x, tv.x), 0.f);
            v.y = fmaxf(fmaf(sv.y, g4.y+h4.y, tv.y), 0.f);
            v.z = fmaxf(fmaf(sv.z, g4.z+h4.z, tv.z), 0.f);
            v.w = fmaxf(fmaf(sv.w, g4.w+h4.w, tv.w), 0.f);
            *(float4*)(xsp + swi4(col,c4)) = v;
        }
        __syncthreads();
        int Tn = T + GRID;
        int nreg = 0;
        bool hasN2 = false;
        if (Tn < 4096) {
            float* xsn = xs + (p^1)*8192;
            const int* ib = idxb + ((t+1)&1)*128;
            int bb = Tn >> 9;
#pragma unroll
            for (int k = 0; k < 8; k++) {
                int i = tid + k*256, col = i>>4, c4 = i&15;
                int m = ib[col];
                cp_async16(shaddr(xsn + swi4(col,c4)),
                           g_G + (((size_t)(bb<<12) + m)<<6) + (c4<<2));
            }
            if (tid < 128) cp_async16(shaddr(hs + (p^1)*512 + tid*4),
                                      g_H + (size_t)Tn*512 + tid*4);
            cp_commit();
            int T2 = T + 2*GRID;
            if (tid < 128 && T2 < 4096) { nreg = g_idx[T2*128 + tid]; hasN2 = true; }
        }
        int ty = tid >> 5, tx = tid & 31;
        int o0 = ty * 8;
        ull acc2[8][4];
#pragma unroll
        for (int i = 0; i < 8; i++)
#pragma unroll
            for (int j = 0; j < 4; j++) acc2[i][j] = 0ull;
#pragma unroll
        for (int c4 = 0; c4 < 16; c4++) {
            ulonglong2 xv[4];
#pragma unroll
            for (int j = 0; j < 4; j++) xv[j] = *(const ulonglong2*)(xsp + swi4(tx + 32*j, c4));
#pragma unroll
            for (int ih = 0; ih < 2; ih++) {
                ulonglong2 wv[4];
#pragma unroll
                for (int i = 0; i < 4; i++) wv[i] = *(const ulonglong2*)(Ws + swi4(o0 + ih*4 + i, c4));
#pragma unroll
                for (int i = 0; i < 4; i++)
#pragma unroll
                    for (int j = 0; j < 4; j++) {
                        FMA2(acc2[ih*4+i][j], wv[i].x, xv[j].x);
                        FMA2(acc2[ih*4+i][j], wv[i].y, xv[j].y);
                    }
            }
        }
        float v[8][4];
#pragma unroll
        for (int i = 0; i < 8; i++)
#pragma unroll
            for (int j = 0; j < 4; j++) v[i][j] = lo32(acc2[i][j]) + hi32(acc2[i][j]);
#pragma unroll
        for (int j = 0; j < 4; j++) {
            int col = tx + 32*j;
            float* yp = g_y1 + (((size_t)(pbase + (col>>4))*16 + (col&15))<<6) + o0;
            *(float4*)yp       = make_float4(v[0][j], v[1][j], v[2][j], v[3][j]);
            *(float4*)(yp + 4) = make_float4(v[4][j], v[5][j], v[6][j], v[7][j]);
        }
#pragma unroll
        for (int i = 0; i < 8; i++) {
            float ps = 0.f, pq = 0.f;
#pragma unroll
            for (int j = 0; j < 4; j++) { ps += v[i][j]; pq = fmaf(v[i][j], v[i][j], pq); }
#pragma unroll
            for (int s = 16; s >= 1; s >>= 1) {
                ps += __shfl_xor_sync(0xffffffffu, ps, s);
                pq += __shfl_xor_sync(0xffffffffu, pq, s);
            }
            if (tx == 0) { bsum[o0+i] += ps; bsq[o0+i] += pq; }
        }
        if (hasN2) idxb[(t&1)*128 + tid] = nreg;
        __syncthreads();
        p ^= 1;
    }
    if (tid < 64) { atomicAdd(&g_sum1[tid], (double)bsum[tid]); atomicAdd(&g_sq1[tid], (double)bsq[tid]); }
}

// ---------------- layer2: persistent, o-channel-split (2 halves), cp.async double-buffered ----------------
__global__ __launch_bounds__(256,2) void layer2_kernel(const float* __restrict__ W2,
                                                       const float* __restrict__ gg1,
                                                       const float* __restrict__ bb1) {
    extern __shared__ float sm[];
    float* Ws   = sm;
    float* xs   = sm + 4096;
    float* s1s  = sm + 4096 + 16384;
    float* t1s  = s1s + 64;
    float* bsum = t1s + 64;
    float* bsq  = bsum + 64;
    int tid = threadIdx.x;
    int oh = blockIdx.x & 1;
    int T0 = blockIdx.x >> 1;
    int GRID2 = gridDim.x >> 1;
    for (int i = tid; i < 4096; i += 256) {
        int o = i>>6, c = i&63;
        Ws[swi(o,c)] = W2[(oh*64 + o)*64 + c];
    }
    if (tid < 64) {
        const double cnt = (double)BB*NN*KK;
        double mean = g_sum1[tid] / cnt;
        double var  = g_sq1[tid] / cnt - mean*mean;
        float sv = gg1[tid] * rsqrtf((float)var + 1e-5f);
        s1s[tid] = sv;
        t1s[tid] = bb1[tid] - (float)mean * sv;
        bsum[tid] = 0.f; bsq[tid] = 0.f;
    }
    __syncthreads();
#pragma unroll
    for (int k = 0; k < 8; k++) {
        int i = tid + k*256, col = i>>4, c4 = i&15;
        cp_async16(shaddr(xs + swi4(col,c4)), g_y1 + (size_t)T0*8192 + col*64 + (c4<<2));
    }
    cp_commit();
    int p = 0;
    for (int T = T0; T < 4096; T += GRID2) {
        int pbase = T*8;
        float* xsp = xs + p*8192;
        cp_wait0(); __syncthreads();
        const float4* s1v = (const float4*)s1s;
        const float4* t1v = (const float4*)t1s;
#pragma unroll
        for (int k = 0; k < 8; k++) {
            int i = tid + k*256, col = i>>4, c4 = i&15;
            float4 y = *(float4*)(xsp + swi4(col,c4));
            float4 sv = s1v[c4], tv = t1v[c4], v;
            v.x = fmaxf(fmaf(sv.x, y.x, tv.x), 0.f);
            v.y = fmaxf(fmaf(sv.y, y.y, tv.y), 0.f);
            v.z = fmaxf(fmaf(sv.z, y.z, tv.z), 0.f);
            v.w = fmaxf(fmaf(sv.w, y.w, tv.w), 0.f);
            *(float4*)(xsp + swi4(col,c4)) = v;
        }
        __syncthreads();
        int Tn = T + GRID2;
        if (Tn < 4096) {
            float* xsn = xs + (p^1)*8192;
#pragma unroll
            for (int k = 0; k < 8; k++) {
                int i = tid + k*256, col = i>>4, c4 = i&15;
                cp_async16(shaddr(xsn + swi4(col,c4)),
                           g_y1 + (size_t)Tn*8192 + col*64 + (c4<<2));
            }
            cp_commit();
        }
        int ty = tid >> 5, tx = tid & 31;
        int o0 = ty * 8;
        ull acc2[8][4];
#pragma unroll
        for (int i = 0; i < 8; i++)
#pragma unroll
            for (int j = 0; j < 4; j++) acc2[i][j] = 0ull;
#pragma unroll
        for (int c4 = 0; c4 < 16; c4++) {
            ulonglong2 xv[4];
#pragma unroll
            for (int j = 0; j < 4; j++) xv[j] = *(const ulonglong2*)(xsp + swi4(tx + 32*j, c4));
#pragma unroll
            for (int ih = 0; ih < 2; ih++) {
                ulonglong2 wv[4];
#pragma unroll
                for (int i = 0; i < 4; i++) wv[i] = *(const ulonglong2*)(Ws + swi4(o0 + ih*4 + i, c4));
#pragma unroll
                for (int i = 0; i < 4; i++)
#pragma unroll
                    for (int j = 0; j < 4; j++) {
                        FMA2(acc2[ih*4+i][j], wv[i].x, xv[j].x);
                        FMA2(acc2[ih*4+i][j], wv[i].y, xv[j].y);
                    }
            }
        }
        float v[8][4];
#pragma unroll
        for (int i = 0; i < 8; i++)
#pragma unroll
            for (int j = 0; j < 4; j++) v[i][j] = lo32(acc2[i][j]) + hi32(acc2[i][j]);
#pragma unroll
        for (int i = 0; i < 8; i++) {
            float ps = 0.f, pq = 0.f;
#pragma unroll
            for (int j = 0; j < 4; j++) { ps += v[i][j]; pq = fmaf(v[i][j], v[i][j], pq); }
#pragma unroll
            for (int s = 16; s >= 1; s >>= 1) {
                ps += __shfl_xor_sync(0xffffffffu, ps, s);
                pq += __shfl_xor_sync(0xffffffffu, pq, s);
            }
            if (tx == 0) { bsum[o0+i] += ps; bsq[o0+i] += pq; }
        }
#pragma unroll
        for (int i = 0; i < 8; i++)
#pragma unroll
            for (int j = 0; j < 4; j++) {
                float mx = v[i][j], mn = v[i][j];
#pragma unroll
                for (int s = 8; s >= 1; s >>= 1) {
                    mx = fmaxf(mx, __shfl_xor_sync(0xffffffffu, mx, s, 16));
                    mn = fminf(mn, __shfl_xor_sync(0xffffffffu, mn, s, 16));
                }
                if ((tx & 15) == 0) {
                    int pp = 2*j + (tx >> 4);
                    g_mx[(size_t)(pbase + pp)*128 + oh*64 + o0 + i] = mx;
                    g_mn[(size_t)(pbase + pp)*128 + oh*64 + o0 + i] = mn;
                }
            }
        __syncthreads();
        p ^= 1;
    }
    if (tid < 64) { atomicAdd(&g_sum2[oh*64 + tid], (double)bsum[tid]); atomicAdd(&g_sq2[oh*64 + tid], (double)bsq[tid]); }
}

__global__ void final_out_kernel(float* __restrict__ out,
                                 const float* __restrict__ gg2,
                                 const float* __restrict__ bb2) {
    __shared__ float tile[32][129];
    __shared__ float s2s[128], t2s[128];
    int tid = threadIdx.x;
    if (tid < 128) {
        const double cnt = (double)BB*NN*KK;
        double mean = g_sum2[tid] / cnt;
        double var  = g_sq2[tid] / cnt - mean*mean;
        float sv = gg2[tid] * rsqrtf((float)var + 1e-5f);
        s2s[tid] = sv;
        t2s[tid] = bb2[tid] - (float)mean * sv;
    }
    __syncthreads();
    int bn0 = blockIdx.x * 32;
    int b = bn0 >> 12, n0 = bn0 & 4095;
    for (int i = tid; i < 32*128; i += 256) {
        int r = i >> 7, o = i & 127;
        float s = s2s[o], t = t2s[o];
        size_t p = (size_t)(bn0 + r)*128 + o;
        float v = fmaxf(fmaf(s, g_mx[p], t), fmaf(s, g_mn[p], t));
        tile[r][o] = fmaxf(v, 0.f);
    }
    __syncthreads();
    for (int i = tid; i < 4096; i += 256) {
        int o = i >> 5, j = i & 31;
        out[(size_t)b*128*NN + o*NN + n0 + j] = tile[j][o];
    }
}

extern "C" void kernel_launch(void* const* d_in, const int* in_sizes, int n_in,
                              void* d_out, int out_size) {
    const float* pos1   = (const float*)d_in[0];
    const float* pos1re = (const float*)d_in[1];
    const float* pos2   = (const float*)d_in[2];
    const float* f1     = (const float*)d_in[3];
    const float* f2     = (const float*)d_in[4];
    const float* W0 = (const float*)d_in[6];
    const float* g0 = (const float*)d_in[7];
    const float* b0 = (const float*)d_in[8];
    const float* W1 = (const float*)d_in[9];
    const float* g1 = (const float*)d_in[10];
    const float* b1 = (const float*)d_in[11];
    const float* W2 = (const float*)d_in[12];
    const float* g2 = (const float*)d_in[13];
    const float* b2 = (const float*)d_in[14];

    float* out = (float*)d_out;
    const size_t featElems = (size_t)BB*128*NN;
    const size_t posElems  = (size_t)BB*3*NN;
    float* featOut = out + ((size_t)out_size - featElems);
    if ((size_t)out_size > featElems)
        cudaMemcpyAsync(out, pos1, posElems*sizeof(float), cudaMemcpyDeviceToDevice);

    static bool attrs_set = false;
    if (!attrs_set) {
        cudaFuncSetAttribute(layer1_kernel, cudaFuncAttributeMaxDynamicSharedMemorySize, 88064);
        cudaFuncSetAttribute(layer2_kernel, cudaFuncAttributeMaxDynamicSharedMemorySize, 83200);
        attrs_set = true;
    }

    knn_kernel<<<dim3(32, 8), 128>>>(pos1re, pos2);
    gh_kernel<<<512, 256>>>(pos1, pos2, f1, f2, W0);
    stats0_kernel<<<2048, 256>>>();
    layer1_kernel<<<304, 256, 88064>>>(W1, g0, b0);
    layer2_kernel<<<304, 256, 83200>>>(W2, g1, b1);
    final_out_kernel<<<1024, 256>>>(featOut, g2, b2);
}

// round 15
// speedup vs baseline: 1.3181x; 1.3181x over previous
#include <cuda_runtime.h>
#include <cstdint>
#include <math.h>

#define BB 8
#define NN 4096
#define KK 16

typedef unsigned long long ull;
#define FMA2(d,a,b) asm("fma.rn.f32x2 %0, %1, %2, %0;" : "+l"(d) : "l"(a), "l"(b))

__device__ int    g_idx[BB*NN*KK];
__device__ float  g_kd[2*BB*NN*KK];
__device__ int    g_ki[2*BB*NN*KK];
__device__ float  g_G[BB*NN*64];
__device__ float  g_H[BB*NN*64];
__device__ float  g_y1[(size_t)BB*NN*KK*64];
__device__ float  g_mx[(size_t)BB*NN*128];
__device__ float  g_mn[(size_t)BB*NN*128];
__device__ double g_sum0[64], g_sq0[64], g_sum1[64], g_sq1[64], g_sum2[128], g_sq2[128];

__device__ __forceinline__ int swi(int col, int c) {
    return (col << 6) + ((((c >> 2) ^ col) & 15) << 2) + (c & 3);
}
__device__ __forceinline__ int swi4(int col, int chunk) {
    return (col << 6) + (((chunk ^ col) & 15) << 2);
}
__device__ __forceinline__ float lo32(ull u) { return __uint_as_float((unsigned)u); }
__device__ __forceinline__ float hi32(ull u) { return __uint_as_float((unsigned)(u >> 32)); }
__device__ __forceinline__ unsigned int shaddr(const void* p) {
    return (unsigned int)__cvta_generic_to_shared(p);
}
__device__ __forceinline__ void cp_async16(unsigned int s, const void* g) {
    asm volatile("cp.async.cg.shared.global [%0], [%1], 16;" :: "r"(s), "l"(g) : "memory");
}
__device__ __forceinline__ void cp_commit() {
    asm volatile("cp.async.commit_group;" ::: "memory");
}
__device__ __forceinline__ void cp_wait0() {
    asm volatile("cp.async.wait_group 0;" ::: "memory");
}

// merge kept[16] (sorted asc) with per-lane smem buffer (cnt entries) -> new sorted kept
__device__ __forceinline__ void topk_merge(float* kd, int* ki, int& cnt, float& thresh,
                                           const float* bufd, const int* bufi, int lane) {
    float md[32]; int mi[32];
#pragma unroll
    for (int i = 0; i < 16; i++) { md[i] = kd[i]; mi[i] = ki[i]; }
#pragma unroll
    for (int i = 0; i < 16; i++) {
        bool v = (i < cnt);
        md[16+i] = v ? bufd[i*128 + lane] : 3.4e38f;
        mi[16+i] = v ? bufi[i*128 + lane] : 0;
    }
#pragma unroll
    for (int k = 2; k <= 32; k <<= 1)
#pragma unroll
        for (int j = k >> 1; j > 0; j >>= 1)
#pragma unroll
            for (int i = 0; i < 32; i++) {
                int l = i ^ j;
                if (l > i) {
                    bool dir = ((i & k) == 0);
                    bool sw = dir ? (md[l] < md[i]) : (md[l] > md[i]);
                    float td = sw ? md[l] : md[i]; float tD = sw ? md[i] : md[l];
                    int   ti = sw ? mi[l] : mi[i]; int   tI = sw ? mi[i] : mi[l];
                    md[i] = td; md[l] = tD; mi[i] = ti; mi[l] = tI;
                }
            }
#pragma unroll
    for (int i = 0; i < 16; i++) { kd[i] = md[i]; ki[i] = mi[i]; }
    thresh = kd[15];
    cnt = 0;
}

// ---------------- KNN over a 2048-ref chunk; buffered top-k ----------------
__global__ __launch_bounds__(128) void knn_part_kernel(const float* __restrict__ q,
                                                       const float* __restrict__ r) {
    if (blockIdx.x == 0 && blockIdx.y == 0 && blockIdx.z == 0) {
        int i = threadIdx.x;
        if (i < 64) { g_sum0[i]=0.0; g_sq0[i]=0.0; g_sum1[i]=0.0; g_sq1[i]=0.0; }
        if (i < 128){ g_sum2[i]=0.0; g_sq2[i]=0.0; }
    }
    __shared__ float4 refs[512];
    __shared__ float bufd[16*128];
    __shared__ int   bufi[16*128];
    int lane = threadIdx.x;
    int chunk = blockIdx.z;
    int b = blockIdx.y;
    int n = blockIdx.x * 128 + lane;
    const float* qb = q + b*3*NN;
    float qx = qb[n], qy = qb[NN+n], qz = qb[2*NN+n];
    float q2 = qx*qx + qy*qy + qz*qz;
    float kd[16]; int ki[16];
#pragma unroll
    for (int i = 0; i < 16; i++) { kd[i] = 3.4e38f; ki[i] = 0; }
    float thresh = 3.4e38f;
    int cnt = 0;
    const float* rb = r + b*3*NN;
    int t0 = chunk * 2048;
    for (int t = t0; t < t0 + 2048; t += 512) {
        __syncthreads();
        for (int j = lane; j < 512; j += 128) {
            float rx = rb[t+j], ry = rb[NN+t+j], rz = rb[2*NN+t+j];
            refs[j] = make_float4(rx, ry, rz, rx*rx + ry*ry + rz*rz);
        }
        __syncthreads();
#pragma unroll 2
        for (int j = 0; j < 512; j++) {
            float4 rv = refs[j];
            float dot = fmaf(qx, rv.x, fmaf(qy, rv.y, qz*rv.z));
            float d = fmaf(-2.f, dot, q2 + rv.w);
            if (d < thresh) {
                bufd[cnt*128 + lane] = d;
                bufi[cnt*128 + lane] = t + j;
                cnt++;
            }
            if (__any_sync(0xffffffffu, cnt == 16))
                topk_merge(kd, ki, cnt, thresh, bufd, bufi, lane);
        }
    }
    topk_merge(kd, ki, cnt, thresh, bufd, bufi, lane);
    int base = ((b*NN + n)*2 + chunk)*16;
#pragma unroll
    for (int i = 0; i < 16; i++) { g_kd[base+i] = kd[i]; g_ki[base+i] = ki[i]; }
}

// ---------------- fused: blocks 0-127 = knn merge; blocks 128-639 = G/H GEMM ----------------
__global__ __launch_bounds__(256) void merge_gh_kernel(const float* __restrict__ pos1,
                                                       const float* __restrict__ pos2,
                                                       const float* __restrict__ f1,
                                                       const float* __restrict__ f2,
                                                       const float* __restrict__ W0) {
    __shared__ float Wt[67][32];
    __shared__ float Xs[8][256];
    int tid = threadIdx.x;
    if (blockIdx.x < 128) {
        int bn = blockIdx.x * 256 + tid;
        float da[32]; int ia[32];
        const float* dp = g_kd + (size_t)bn*32;
        const int*   ip = g_ki + (size_t)bn*32;
#pragma unroll
        for (int i = 0; i < 32; i++) { da[i] = dp[i]; ia[i] = ip[i]; }
        int a = 0, c = 16;
        int base = bn*16;
#pragma unroll
        for (int o = 0; o < 16; o++) {
            bool takeA = da[a] <= da[c];
            g_idx[base+o] = takeA ? ia[a] : ia[c];
            a += takeA; c += !takeA;
        }
        return;
    }
    int g = blockIdx.x - 128;
    int isH = g >> 8;
    int oh  = (g >> 7) & 1;
    int bt  = g & 127;
    int b = bt >> 4, m0 = (bt & 15) * 256;
    const float* pos  = isH ? pos1 : pos2;
    const float* feat = isH ? f1   : f2;
    for (int i = tid; i < 32*67; i += 256) {
        int o = i & 31, c = i >> 5;
        int gc = (c < 3) ? c : (isH ? c + 64 : c);
        Wt[c][o] = W0[(oh*32 + o)*131 + gc];
    }
    __syncthreads();
    int m = m0 + tid;
    const float* pp = pos + b*3*NN;
    float p0 = pp[m], p1 = pp[NN+m], p2 = pp[2*NN+m];
    if (isH) { p0 = -p0; p1 = -p1; p2 = -p2; }
    float acc[32];
#pragma unroll
    for (int o = 0; o < 32; o++)
        acc[o] = fmaf(Wt[0][o], p0, fmaf(Wt[1][o], p1, Wt[2][o]*p2));
    const float* fb = feat + (size_t)b*64*NN + m0;
    for (int cc = 0; cc < 64; cc += 8) {
        __syncthreads();
        for (int i = tid; i < 2048; i += 256) {
            int r = i >> 8, mm = i & 255;
            Xs[r][mm] = fb[(size_t)(cc + r)*NN + mm];
        }
        __syncthreads();
#pragma unroll
        for (int r = 0; r < 8; r++) {
            float x = Xs[r][tid];
            const float* w = &Wt[3 + cc + r][0];
#pragma unroll
            for (int o4 = 0; o4 < 32; o4 += 4) {
                float4 wv = *(const float4*)(w + o4);
                acc[o4+0] = fmaf(wv.x, x, acc[o4+0]);
                acc[o4+1] = fmaf(wv.y, x, acc[o4+1]);
                acc[o4+2] = fmaf(wv.z, x, acc[o4+2]);
                acc[o4+3] = fmaf(wv.w, x, acc[o4+3]);
            }
        }
    }
    float* outp = (isH ? g_H : g_G) + ((size_t)((b<<12) + m) << 6) + oh*32;
#pragma unroll
    for (int o4 = 0; o4 < 32; o4 += 4)
        *(float4*)(outp + o4) = make_float4(acc[o4], acc[o4+1], acc[o4+2], acc[o4+3]);
}

__global__ void stats0_kernel() {
    __shared__ float bsum[64], bsq[64];
    int tid = threadIdx.x;
    if (tid < 64) { bsum[tid] = 0.f; bsq[tid] = 0.f; }
    __syncthreads();
    int warp = tid >> 5, lane = tid & 31;
    int c4 = lane & 15, r2 = lane >> 4;
    int p0 = blockIdx.x*16 + warp*2;
    int p1 = p0 + 1;
    int b = p0 >> 12;
    int mk = g_idx[p0*16 + lane];
    float4 hA = *(const float4*)(g_H + (size_t)p0*64 + c4*4);
    float4 hB = *(const float4*)(g_H + (size_t)p1*64 + c4*4);
    float4 s = make_float4(0,0,0,0), qq = make_float4(0,0,0,0);
#pragma unroll
    for (int st = 0; st < 16; st++) {
        int row = 2*st + r2;
        int m = __shfl_sync(0xffffffffu, mk, row);
        float4 g4 = *(const float4*)(g_G + ((size_t)((b<<12) + m) << 6) + (c4<<2));
        float4 h = (row < 16) ? hA : hB;
        float vx = g4.x + h.x, vy = g4.y + h.y, vz = g4.z + h.z, vw = g4.w + h.w;
        s.x += vx; s.y += vy; s.z += vz; s.w += vw;
        qq.x = fmaf(vx, vx, qq.x); qq.y = fmaf(vy, vy, qq.y);
        qq.z = fmaf(vz, vz, qq.z); qq.w = fmaf(vw, vw, qq.w);
    }
    s.x += __shfl_xor_sync(0xffffffffu, s.x, 16);
    s.y += __shfl_xor_sync(0xffffffffu, s.y, 16);
    s.z += __shfl_xor_sync(0xffffffffu, s.z, 16);
    s.w += __shfl_xor_sync(0xffffffffu, s.w, 16);
    qq.x += __shfl_xor_sync(0xffffffffu, qq.x, 16);
    qq.y += __shfl_xor_sync(0xffffffffu, qq.y, 16);
    qq.z += __shfl_xor_sync(0xffffffffu, qq.z, 16);
    qq.w += __shfl_xor_sync(0xffffffffu, qq.w, 16);
    if (lane < 16) {
        atomicAdd(&bsum[c4*4+0], s.x); atomicAdd(&bsum[c4*4+1], s.y);
        atomicAdd(&bsum[c4*4+2], s.z); atomicAdd(&bsum[c4*4+3], s.w);
        atomicAdd(&bsq[c4*4+0], qq.x); atomicAdd(&bsq[c4*4+1], qq.y);
        atomicAdd(&bsq[c4*4+2], qq.z); atomicAdd(&bsq[c4*4+3], qq.w);
    }
    __syncthreads();
    if (tid < 64) { atomicAdd(&g_sum0[tid], (double)bsum[tid]); atomicAdd(&g_sq0[tid], (double)bsq[tid]); }
}

// ---------------- layer1: persistent, cp.async double-buffered ----------------
__global__ __launch_bounds__(256,2) void layer1_kernel(const float* __restrict__ W1,
                                                       const float* __restrict__ gg0,
                                                       const float* __restrict__ bb0) {
    extern __shared__ float sm[];
    float* Ws   = sm;
    float* xs   = sm + 4096;
    float* hs   = sm + 4096 + 16384;
    float* s0s  = hs + 1024;
    float* t0s  = s0s + 64;
    float* bsum = t0s + 64;
    float* bsq  = bsum + 64;
    int*   idxb = (int*)(bsq + 64);
    int tid = threadIdx.x;
    for (int i = tid; i < 4096; i += 256) { int o=i>>6, c=i&63; Ws[swi(o,c)] = W1[i]; }
    if (tid < 64) {
        const double cnt = (double)BB*NN*KK;
        double mean = g_sum0[tid] / cnt;
        double var  = g_sq0[tid] / cnt - mean*mean;
        float sv = gg0[tid] * rsqrtf((float)var + 1e-5f);
        s0s[tid] = sv;
        t0s[tid] = bb0[tid] - (float)mean * sv;
        bsum[tid] = 0.f; bsq[tid] = 0.f;
    }
    int GRID = gridDim.x;
    int T0 = blockIdx.x;
    if (tid < 128) {
        idxb[tid] = g_idx[T0*128 + tid];
        if (T0 + GRID < 4096) idxb[128 + tid] = g_idx[(T0+GRID)*128 + tid];
        cp_async16(shaddr(hs + tid*4), g_H + (size_t)T0*512 + tid*4);
    }
    __syncthreads();
    {
        int bb = T0 >> 9;
#pragma unroll
        for (int k = 0; k < 8; k++) {
            int i = tid + k*256, col = i>>4, c4 = i&15;
            int m = idxb[col];
            cp_async16(shaddr(xs + swi4(col,c4)),
                       g_G + (((size_t)(bb<<12) + m)<<6) + (c4<<2));
        }
    }
    cp_commit();
    int p = 0, t = 0;
    for (int T = T0; T < 4096; T += GRID, t++) {
        int pbase = T*8;
        float* xsp = xs + p*8192;
        float* hsp = hs + p*512;
        cp_wait0(); __syncthreads();
        const float4* s0v = (const float4*)s0s;
        const float4* t0v = (const float4*)t0s;
#pragma unroll
        for (int k = 0; k < 8; k++) {
            int i = tid + k*256, col = i>>4, c4 = i&15;
            float4 g4 = *(float4*)(xsp + swi4(col,c4));
            float4 h4 = *(float4*)(hsp + (col>>4)*64 + (c4<<2));
            float4 sv = s0v[c4], tv = t0v[c4], v;
            v.x = fmaxf(fmaf(sv.x, g4.x+h4.x, tv.x), 0.f);
            v.y = fmaxf(fmaf(sv.y, g4.y+h4.y, tv.y), 0.f);
            v.z = fmaxf(fmaf(sv.z, g4.z+h4.z, tv.z), 0.f);
            v.w = fmaxf(fmaf(sv.w, g4.w+h4.w, tv.w), 0.f);
            *(float4*)(xsp + swi4(col,c4)) = v;
        }
        __syncthreads();
        int Tn = T + GRID;
        int nreg = 0;
        bool hasN2 = false;
        if (Tn < 4096) {
            float* xsn = xs + (p^1)*8192;
            const int* ib = idxb + ((t+1)&1)*128;
            int bb = Tn >> 9;
#pragma unroll
            for (int k = 0; k < 8; k++) {
                int i = tid + k*256, col = i>>4, c4 = i&15;
                int m = ib[col];
                cp_async16(shaddr(xsn + swi4(col,c4)),
                           g_G + (((size_t)(bb<<12) + m)<<6) + (c4<<2));
            }
            if (tid < 128) cp_async16(shaddr(hs + (p^1)*512 + tid*4),
                                      g_H + (size_t)Tn*512 + tid*4);
            cp_commit();
            int T2 = T + 2*GRID;
            if (tid < 128 && T2 < 4096) { nreg = g_idx[T2*128 + tid]; hasN2 = true; }
        }
        int ty = tid >> 5, tx = tid & 31;
        int o0 = ty * 8;
        ull acc2[8][4];
#pragma unroll
        for (int i = 0; i < 8; i++)
#pragma unroll
            for (int j = 0; j < 4; j++) acc2[i][j] = 0ull;
#pragma unroll
        for (int c4 = 0; c4 < 16; c4++) {
            ulonglong2 xv[4];
#pragma unroll
            for (int j = 0; j < 4; j++) xv[j] = *(const ulonglong2*)(xsp + swi4(tx + 32*j, c4));
#pragma unroll
            for (int ih = 0; ih < 2; ih++) {
                ulonglong2 wv[4];
#pragma unroll
                for (int i = 0; i < 4; i++) wv[i] = *(const ulonglong2*)(Ws + swi4(o0 + ih*4 + i, c4));
#pragma unroll
                for (int i = 0; i < 4; i++)
#pragma unroll
                    for (int j = 0; j < 4; j++) {
                        FMA2(acc2[ih*4+i][j], wv[i].x, xv[j].x);
                        FMA2(acc2[ih*4+i][j], wv[i].y, xv[j].y);
                    }
            }
        }
        float v[8][4];
#pragma unroll
        for (int i = 0; i < 8; i++)
#pragma unroll
            for (int j = 0; j < 4; j++) v[i][j] = lo32(acc2[i][j]) + hi32(acc2[i][j]);
#pragma unroll
        for (int j = 0; j < 4; j++) {
            int col = tx + 32*j;
            float* yp = g_y1 + (((size_t)(pbase + (col>>4))*16 + (col&15))<<6) + o0;
            *(float4*)yp       = make_float4(v[0][j], v[1][j], v[2][j], v[3][j]);
            *(float4*)(yp + 4) = make_float4(v[4][j], v[5][j], v[6][j], v[7][j]);
        }
#pragma unroll
        for (int i = 0; i < 8; i++) {
            float ps = 0.f, pq = 0.f;
#pragma unroll
            for (int j = 0; j < 4; j++) { ps += v[i][j]; pq = fmaf(v[i][j], v[i][j], pq); }
#pragma unroll
            for (int s = 16; s >= 1; s >>= 1) {
                ps += __shfl_xor_sync(0xffffffffu, ps, s);
                pq += __shfl_xor_sync(0xffffffffu, pq, s);
            }
            if (tx == 0) { bsum[o0+i] += ps; bsq[o0+i] += pq; }
        }
        if (hasN2) idxb[(t&1)*128 + tid] = nreg;
        __syncthreads();
        p ^= 1;
    }
    if (tid < 64) { atomicAdd(&g_sum1[tid], (double)bsum[tid]); atomicAdd(&g_sq1[tid], (double)bsq[tid]); }
}

// ---------------- layer2: persistent, o-channel-split (2 halves), cp.async double-buffered ----------------
__global__ __launch_bounds__(256,2) void layer2_kernel(const float* __restrict__ W2,
                                                       const float* __restrict__ gg1,
                                                       const float* __restrict__ bb1) {
    extern __shared__ float sm[];
    float* Ws   = sm;
    float* xs   = sm + 4096;
    float* s1s  = sm + 4096 + 16384;
    float* t1s  = s1s + 64;
    float* bsum = t1s + 64;
    float* bsq  = bsum + 64;
    int tid = threadIdx.x;
    int oh = blockIdx.x & 1;
    int T0 = blockIdx.x >> 1;
    int GRID2 = gridDim.x >> 1;
    for (int i = tid; i < 4096; i += 256) {
        int o = i>>6, c = i&63;
        Ws[swi(o,c)] = W2[(oh*64 + o)*64 + c];
    }
    if (tid < 64) {
        const double cnt = (double)BB*NN*KK;
        double mean = g_sum1[tid] / cnt;
        double var  = g_sq1[tid] / cnt - mean*mean;
        float sv = gg1[tid] * rsqrtf((float)var + 1e-5f);
        s1s[tid] = sv;
        t1s[tid] = bb1[tid] - (float)mean * sv;
        bsum[tid] = 0.f; bsq[tid] = 0.f;
    }
    __syncthreads();
#pragma unroll
    for (int k = 0; k < 8; k++) {
        int i = tid + k*256, col = i>>4, c4 = i&15;
        cp_async16(shaddr(xs + swi4(col,c4)), g_y1 + (size_t)T0*8192 + col*64 + (c4<<2));
    }
    cp_commit();
    int p = 0;
    for (int T = T0; T < 4096; T += GRID2) {
        int pbase = T*8;
        float* xsp = xs + p*8192;
        cp_wait0(); __syncthreads();
        const float4* s1v = (const float4*)s1s;
        const float4* t1v = (const float4*)t1s;
#pragma unroll
        for (int k = 0; k < 8; k++) {
            int i = tid + k*256, col = i>>4, c4 = i&15;
            float4 y = *(float4*)(xsp + swi4(col,c4));
            float4 sv = s1v[c4], tv = t1v[c4], v;
            v.x = fmaxf(fmaf(sv.x, y.x, tv.x), 0.f);
            v.y = fmaxf(fmaf(sv.y, y.y, tv.y), 0.f);
            v.z = fmaxf(fmaf(sv.z, y.z, tv.z), 0.f);
            v.w = fmaxf(fmaf(sv.w, y.w, tv.w), 0.f);
            *(float4*)(xsp + swi4(col,c4)) = v;
        }
        __syncthreads();
        int Tn = T + GRID2;
        if (Tn < 4096) {
            float* xsn = xs + (p^1)*8192;
#pragma unroll
            for (int k = 0; k < 8; k++) {
                int i = tid + k*256, col = i>>4, c4 = i&15;
                cp_async16(shaddr(xsn + swi4(col,c4)),
                           g_y1 + (size_t)Tn*8192 + col*64 + (c4<<2));
            }
            cp_commit();
        }
        int ty = tid >> 5, tx = tid & 31;
        int o0 = ty * 8;
        ull acc2[8][4];
#pragma unroll
        for (int i = 0; i < 8; i++)
#pragma unroll
            for (int j = 0; j < 4; j++) acc2[i][j] = 0ull;
#pragma unroll
        for (int c4 = 0; c4 < 16; c4++) {
            ulonglong2 xv[4];
#pragma unroll
            for (int j = 0; j < 4; j++) xv[j] = *(const ulonglong2*)(xsp + swi4(tx + 32*j, c4));
#pragma unroll
            for (int ih = 0; ih < 2; ih++) {
                ulonglong2 wv[4];
#pragma unroll
                for (int i = 0; i < 4; i++) wv[i] = *(const ulonglong2*)(Ws + swi4(o0 + ih*4 + i, c4));
#pragma unroll
                for (int i = 0; i < 4; i++)
#pragma unroll
                    for (int j = 0; j < 4; j++) {
                        FMA2(acc2[ih*4+i][j], wv[i].x, xv[j].x);
                        FMA2(acc2[ih*4+i][j], wv[i].y, xv[j].y);
                    }
            }
        }
        float v[8][4];
#pragma unroll
        for (int i = 0; i < 8; i++)
#pragma unroll
            for (int j = 0; j < 4; j++) v[i][j] = lo32(acc2[i][j]) + hi32(acc2[i][j]);
#pragma unroll
        for (int i = 0; i < 8; i++) {
            float ps = 0.f, pq = 0.f;
#pragma unroll
            for (int j = 0; j < 4; j++) { ps += v[i][j]; pq = fmaf(v[i][j], v[i][j], pq); }
#pragma unroll
            for (int s = 16; s >= 1; s >>= 1) {
                ps += __shfl_xor_sync(0xffffffffu, ps, s);
                pq += __shfl_xor_sync(0xffffffffu, pq, s);
            }
            if (tx == 0) { bsum[o0+i] += ps; bsq[o0+i] += pq; }
        }
#pragma unroll
        for (int i = 0; i < 8; i++)
#pragma unroll
            for (int j = 0; j < 4; j++) {
                float mx = v[i][j], mn = v[i][j];
#pragma unroll
                for (int s = 8; s >= 1; s >>= 1) {
                    mx = fmaxf(mx, __shfl_xor_sync(0xffffffffu, mx, s, 16));
                    mn = fminf(mn, __shfl_xor_sync(0xffffffffu, mn, s, 16));
                }
                if ((tx & 15) == 0) {
                    int pp = 2*j + (tx >> 4);
                    g_mx[(size_t)(pbase + pp)*128 + oh*64 + o0 + i] = mx;
                    g_mn[(size_t)(pbase + pp)*128 + oh*64 + o0 + i] = mn;
                }
            }
        __syncthreads();
        p ^= 1;
    }
    if (tid < 64) { atomicAdd(&g_sum2[oh*64 + tid], (double)bsum[tid]); atomicAdd(&g_sq2[oh*64 + tid], (double)bsq[tid]); }
}

__global__ void final_out_kernel(float* __restrict__ out,
                                 const float* __restrict__ gg2,
                                 const float* __restrict__ bb2) {
    __shared__ float tile[32][129];
    __shared__ float s2s[128], t2s[128];
    int tid = threadIdx.x;
    if (tid < 128) {
        const double cnt = (double)BB*NN*KK;
        double mean = g_sum2[tid] / cnt;
        double var  = g_sq2[tid] / cnt - mean*mean;
        float sv = gg2[tid] * rsqrtf((float)var + 1e-5f);
        s2s[tid] = sv;
        t2s[tid] = bb2[tid] - (float)mean * sv;
    }
    __syncthreads();
    int bn0 = blockIdx.x * 32;
    int b = bn0 >> 12, n0 = bn0 & 4095;
    for (int i = tid; i < 32*128; i += 256) {
        int r = i >> 7, o = i & 127;
        float s = s2s[o], t = t2s[o];
        size_t p = (size_t)(bn0 + r)*128 + o;
        float v = fmaxf(fmaf(s, g_mx[p], t), fmaf(s, g_mn[p], t));
        tile[r][o] = fmaxf(v, 0.f);
    }
    __syncthreads();
    for (int i = tid; i < 4096; i += 256) {
        int o = i >> 5, j = i & 31;
        out[(size_t)b*128*NN + o*NN + n0 + j] = tile[j][o];
    }
}

extern "C" void kernel_launch(void* const* d_in, const int* in_sizes, int n_in,
                              void* d_out, int out_size) {
    const float* pos1   = (const float*)d_in[0];
    const float* pos1re = (const float*)d_in[1];
    const float* pos2   = (const float*)d_in[2];
    const float* f1     = (const float*)d_in[3];
    const float* f2     = (const float*)d_in[4];
    const float* W0 = (const float*)d_in[6];
    const float* g0 = (const float*)d_in[7];
    const float* b0 = (const float*)d_in[8];
    const float* W1 = (const float*)d_in[9];
    const float* g1 = (const float*)d_in[10];
    const float* b1 = (const float*)d_in[11];
    const float* W2 = (const float*)d_in[12];
    const float* g2 = (const float*)d_in[13];
    const float* b2 = (const float*)d_in[14];

    float* out = (float*)d_out;
    const size_t featElems = (size_t)BB*128*NN;
    const size_t posElems  = (size_t)BB*3*NN;
    float* featOut = out + ((size_t)out_size - featElems);
    if ((size_t)out_size > featElems)
        cudaMemcpyAsync(out, pos1, posElems*sizeof(float), cudaMemcpyDeviceToDevice);

    static bool attrs_set = false;
    if (!attrs_set) {
        cudaFuncSetAttribute(layer1_kernel, cudaFuncAttributeMaxDynamicSharedMemorySize, 88064);
        cudaFuncSetAttribute(layer2_kernel, cudaFuncAttributeMaxDynamicSharedMemorySize, 83200);
        attrs_set = true;
    }

    knn_part_kernel<<<dim3(32, 8, 2), 128>>>(pos1re, pos2);
    merge_gh_kernel<<<640, 256>>>(pos1, pos2, f1, f2, W0);
    stats0_kernel<<<2048, 256>>>();
    layer1_kernel<<<304, 256, 88064>>>(W1, g0, b0);
    layer2_kernel<<<304, 256, 83200>>>(W2, g1, b1);
    final_out_kernel<<<1024, 256>>>(featOut, g2, b2);
}

// round 17
// speedup vs baseline: 1.8239x; 1.3837x over previous
#include <cuda_runtime.h>
#include <cuda_bf16.h>
#include <cstdint>
#include <math.h>

#define BB 8
#define NN 4096
#define KK 16

typedef unsigned long long ull;
#define FMA2(d,a,b) asm("fma.rn.f32x2 %0, %1, %2, %0;" : "+l"(d) : "l"(a), "l"(b))

__device__ int    g_idx[BB*NN*KK];
__device__ float  g_kd[2*BB*NN*KK];
__device__ int    g_ki[2*BB*NN*KK];
__device__ float  g_G[BB*NN*64];
__device__ float  g_H[BB*NN*64];
__device__ float  g_y1[(size_t)BB*NN*KK*64];
__device__ float  g_mx[(size_t)BB*NN*128];
__device__ float  g_mn[(size_t)BB*NN*128];
__device__ double g_sum0[64], g_sq0[64], g_sum1[64], g_sq1[64], g_sum2[128], g_sq2[128];

__device__ __forceinline__ int swi(int col, int c) {
    return (col << 6) + ((((c >> 2) ^ col) & 15) << 2) + (c & 3);
}
__device__ __forceinline__ int swi4(int col, int chunk) {
    return (col << 6) + (((chunk ^ col) & 15) << 2);
}
__device__ __forceinline__ float lo32(ull u) { return __uint_as_float((unsigned)u); }
__device__ __forceinline__ float hi32(ull u) { return __uint_as_float((unsigned)(u >> 32)); }
__device__ __forceinline__ unsigned int shaddr(const void* p) {
    return (unsigned int)__cvta_generic_to_shared(p);
}
__device__ __forceinline__ void cp_async16(unsigned int s, const void* g) {
    asm volatile("cp.async.cg.shared.global [%0], [%1], 16;" :: "r"(s), "l"(g) : "memory");
}
__device__ __forceinline__ void cp_commit() {
    asm volatile("cp.async.commit_group;" ::: "memory");
}
__device__ __forceinline__ void cp_wait0() {
    asm volatile("cp.async.wait_group 0;" ::: "memory");
}
__device__ __forceinline__ void mma_bf16(float* c, const unsigned* a, unsigned b0, unsigned b1) {
    asm("mma.sync.aligned.m16n8k16.row.col.f32.bf16.bf16.f32 "
        "{%0,%1,%2,%3}, {%4,%5,%6,%7}, {%8,%9}, {%0,%1,%2,%3};"
        : "+f"(c[0]), "+f"(c[1]), "+f"(c[2]), "+f"(c[3])
        : "r"(a[0]), "r"(a[1]), "r"(a[2]), "r"(a[3]), "r"(b0), "r"(b1));
}
__device__ __forceinline__ unsigned pack_hi2(float x0, float x1) {
    __nv_bfloat16 h0 = __float2bfloat16(x0), h1 = __float2bfloat16(x1);
    return ((unsigned)__bfloat16_as_ushort(h1) << 16) | __bfloat16_as_ushort(h0);
}
__device__ __forceinline__ unsigned pack_lo2(float x0, float x1) {
    __nv_bfloat16 h0 = __float2bfloat16(x0), h1 = __float2bfloat16(x1);
    __nv_bfloat16 l0 = __float2bfloat16(x0 - __bfloat162float(h0));
    __nv_bfloat16 l1 = __float2bfloat16(x1 - __bfloat162float(h1));
    return ((unsigned)__bfloat16_as_ushort(l1) << 16) | __bfloat16_as_ushort(l0);
}

// merge kept[16] (sorted asc) with per-lane smem buffer (cnt entries) -> new sorted kept
__device__ __forceinline__ void topk_merge(float* kd, int* ki, int& cnt, float& thresh,
                                           const float* bufd, const int* bufi, int lane) {
    float md[32]; int mi[32];
#pragma unroll
    for (int i = 0; i < 16; i++) { md[i] = kd[i]; mi[i] = ki[i]; }
#pragma unroll
    for (int i = 0; i < 16; i++) {
        bool v = (i < cnt);
        md[16+i] = v ? bufd[i*128 + lane] : 3.4e38f;
        mi[16+i] = v ? bufi[i*128 + lane] : 0;
    }
#pragma unroll
    for (int k = 2; k <= 32; k <<= 1)
#pragma unroll
        for (int j = k >> 1; j > 0; j >>= 1)
#pragma unroll
            for (int i = 0; i < 32; i++) {
                int l = i ^ j;
                if (l > i) {
                    bool dir = ((i & k) == 0);
                    bool sw = dir ? (md[l] < md[i]) : (md[l] > md[i]);
                    float td = sw ? md[l] : md[i]; float tD = sw ? md[i] : md[l];
                    int   ti = sw ? mi[l] : mi[i]; int   tI = sw ? mi[i] : mi[l];
                    md[i] = td; md[l] = tD; mi[i] = ti; mi[l] = tI;
                }
            }
#pragma unroll
    for (int i = 0; i < 16; i++) { kd[i] = md[i]; ki[i] = mi[i]; }
    thresh = kd[15];
    cnt = 0;
}

__global__ __launch_bounds__(128) void knn_part_kernel(const float* __restrict__ q,
                                                       const float* __restrict__ r) {
    if (blockIdx.x == 0 && blockIdx.y == 0 && blockIdx.z == 0) {
        int i = threadIdx.x;
        if (i < 64) { g_sum0[i]=0.0; g_sq0[i]=0.0; g_sum1[i]=0.0; g_sq1[i]=0.0; }
        if (i < 128){ g_sum2[i]=0.0; g_sq2[i]=0.0; }
    }
    __shared__ float4 refs[512];
    __shared__ float bufd[16*128];
    __shared__ int   bufi[16*128];
    int lane = threadIdx.x;
    int chunk = blockIdx.z;
    int b = blockIdx.y;
    int n = blockIdx.x * 128 + lane;
    const float* qb = q + b*3*NN;
    float qx = qb[n], qy = qb[NN+n], qz = qb[2*NN+n];
    float q2 = qx*qx + qy*qy + qz*qz;
    float kd[16]; int ki[16];
#pragma unroll
    for (int i = 0; i < 16; i++) { kd[i] = 3.4e38f; ki[i] = 0; }
    float thresh = 3.4e38f;
    int cnt = 0;
    const float* rb = r + b*3*NN;
    int t0 = chunk * 2048;
    for (int t = t0; t < t0 + 2048; t += 512) {
        __syncthreads();
        for (int j = lane; j < 512; j += 128) {
            float rx = rb[t+j], ry = rb[NN+t+j], rz = rb[2*NN+t+j];
            refs[j] = make_float4(rx, ry, rz, rx*rx + ry*ry + rz*rz);
        }
        __syncthreads();
#pragma unroll 2
        for (int j = 0; j < 512; j++) {
            float4 rv = refs[j];
            float dot = fmaf(qx, rv.x, fmaf(qy, rv.y, qz*rv.z));
            float d = fmaf(-2.f, dot, q2 + rv.w);
            if (d < thresh) {
                bufd[cnt*128 + lane] = d;
                bufi[cnt*128 + lane] = t + j;
                cnt++;
            }
            if (__any_sync(0xffffffffu, cnt == 16))
                topk_merge(kd, ki, cnt, thresh, bufd, bufi, lane);
        }
    }
    topk_merge(kd, ki, cnt, thresh, bufd, bufi, lane);
    int base = ((b*NN + n)*2 + chunk)*16;
#pragma unroll
    for (int i = 0; i < 16; i++) { g_kd[base+i] = kd[i]; g_ki[base+i] = ki[i]; }
}

__global__ __launch_bounds__(256) void merge_gh_kernel(const float* __restrict__ pos1,
                                                       const float* __restrict__ pos2,
                                                       const float* __restrict__ f1,
                                                       const float* __restrict__ f2,
                                                       const float* __restrict__ W0) {
    __shared__ float Wt[67][32];
    __shared__ float Xs[8][256];
    int tid = threadIdx.x;
    if (blockIdx.x < 128) {
        int bn = blockIdx.x * 256 + tid;
        float da[32]; int ia[32];
        const float* dp = g_kd + (size_t)bn*32;
        const int*   ip = g_ki + (size_t)bn*32;
#pragma unroll
        for (int i = 0; i < 32; i++) { da[i] = dp[i]; ia[i] = ip[i]; }
        int a = 0, c = 16;
        int base = bn*16;
#pragma unroll
        for (int o = 0; o < 16; o++) {
            bool takeA = da[a] <= da[c];
            g_idx[base+o] = takeA ? ia[a] : ia[c];
            a += takeA; c += !takeA;
        }
        return;
    }
    int g = blockIdx.x - 128;
    int isH = g >> 8;
    int oh  = (g >> 7) & 1;
    int bt  = g & 127;
    int b = bt >> 4, m0 = (bt & 15) * 256;
    const float* pos  = isH ? pos1 : pos2;
    const float* feat = isH ? f1   : f2;
    for (int i = tid; i < 32*67; i += 256) {
        int o = i & 31, c = i >> 5;
        int gc = (c < 3) ? c : (isH ? c + 64 : c);
        Wt[c][o] = W0[(oh*32 + o)*131 + gc];
    }
    __syncthreads();
    int m = m0 + tid;
    const float* pp = pos + b*3*NN;
    float p0 = pp[m], p1 = pp[NN+m], p2 = pp[2*NN+m];
    if (isH) { p0 = -p0; p1 = -p1; p2 = -p2; }
    float acc[32];
#pragma unroll
    for (int o = 0; o < 32; o++)
        acc[o] = fmaf(Wt[0][o], p0, fmaf(Wt[1][o], p1, Wt[2][o]*p2));
    const float* fb = feat + (size_t)b*64*NN + m0;
    for (int cc = 0; cc < 64; cc += 8) {
        __syncthreads();
        for (int i = tid; i < 2048; i += 256) {
            int r = i >> 8, mm = i & 255;
            Xs[r][mm] = fb[(size_t)(cc + r)*NN + mm];
        }
        __syncthreads();
#pragma unroll
        for (int r = 0; r < 8; r++) {
            float x = Xs[r][tid];
            const float* w = &Wt[3 + cc + r][0];
#pragma unroll
            for (int o4 = 0; o4 < 32; o4 += 4) {
                float4 wv = *(const float4*)(w + o4);
                acc[o4+0] = fmaf(wv.x, x, acc[o4+0]);
                acc[o4+1] = fmaf(wv.y, x, acc[o4+1]);
                acc[o4+2] = fmaf(wv.z, x, acc[o4+2]);
                acc[o4+3] = fmaf(wv.w, x, acc[o4+3]);
            }
        }
    }
    float* outp = (isH ? g_H : g_G) + ((size_t)((b<<12) + m) << 6) + oh*32;
#pragma unroll
    for (int o4 = 0; o4 < 32; o4 += 4)
        *(float4*)(outp + o4) = make_float4(acc[o4], acc[o4+1], acc[o4+2], acc[o4+3]);
}

__global__ void stats0_kernel() {
    __shared__ float bsum[64], bsq[64];
    int tid = threadIdx.x;
    if (tid < 64) { bsum[tid] = 0.f; bsq[tid] = 0.f; }
    __syncthreads();
    int warp = tid >> 5, lane = tid & 31;
    int c4 = lane & 15, r2 = lane >> 4;
    int p0 = blockIdx.x*16 + warp*2;
    int p1 = p0 + 1;
    int b = p0 >> 12;
    int mk = g_idx[p0*16 + lane];
    float4 hA = *(const float4*)(g_H + (size_t)p0*64 + c4*4);
    float4 hB = *(const float4*)(g_H + (size_t)p1*64 + c4*4);
    float4 s = make_float4(0,0,0,0), qq = make_float4(0,0,0,0);
#pragma unroll
    for (int st = 0; st < 16; st++) {
        int row = 2*st + r2;
        int m = __shfl_sync(0xffffffffu, mk, row);
        float4 g4 = *(const float4*)(g_G + ((size_t)((b<<12) + m) << 6) + (c4<<2));
        float4 h = (row < 16) ? hA : hB;
        float vx = g4.x + h.x, vy = g4.y + h.y, vz = g4.z + h.z, vw = g4.w + h.w;
        s.x += vx; s.y += vy; s.z += vz; s.w += vw;
        qq.x = fmaf(vx, vx, qq.x); qq.y = fmaf(vy, vy, qq.y);
        qq.z = fmaf(vz, vz, qq.z); qq.w = fmaf(vw, vw, qq.w);
    }
    s.x += __shfl_xor_sync(0xffffffffu, s.x, 16);
    s.y += __shfl_xor_sync(0xffffffffu, s.y, 16);
    s.z += __shfl_xor_sync(0xffffffffu, s.z, 16);
    s.w += __shfl_xor_sync(0xffffffffu, s.w, 16);
    qq.x += __shfl_xor_sync(0xffffffffu, qq.x, 16);
    qq.y += __shfl_xor_sync(0xffffffffu, qq.y, 16);
    qq.z += __shfl_xor_sync(0xffffffffu, qq.z, 16);
    qq.w += __shfl_xor_sync(0xffffffffu, qq.w, 16);
    if (lane < 16) {
        atomicAdd(&bsum[c4*4+0], s.x); atomicAdd(&bsum[c4*4+1], s.y);
        atomicAdd(&bsum[c4*4+2], s.z); atomicAdd(&bsum[c4*4+3], s.w);
        atomicAdd(&bsq[c4*4+0], qq.x); atomicAdd(&bsq[c4*4+1], qq.y);
        atomicAdd(&bsq[c4*4+2], qq.z); atomicAdd(&bsq[c4*4+3], qq.w);
    }
    __syncthreads();
    if (tid < 64) { atomicAdd(&g_sum0[tid], (double)bsum[tid]); atomicAdd(&g_sq0[tid], (double)bsq[tid]); }
}

__global__ __launch_bounds__(256,2) void layer1_kernel(const float* __restrict__ W1,
                                                       const float* __restrict__ gg0,
                                                       const float* __restrict__ bb0) {
    extern __shared__ float sm[];
    float* Ws   = sm;
    float* xs   = sm + 4096;
    float* hs   = sm + 4096 + 16384;
    float* s0s  = hs + 1024;
    float* t0s  = s0s + 64;
    float* bsum = t0s + 64;
    float* bsq  = bsum + 64;
    int*   idxb = (int*)(bsq + 64);
    int tid = threadIdx.x;
    for (int i = tid; i < 4096; i += 256) { int o=i>>6, c=i&63; Ws[swi(o,c)] = W1[i]; }
    if (tid < 64) {
        const double cnt = (double)BB*NN*KK;
        double mean = g_sum0[tid] / cnt;
        double var  = g_sq0[tid] / cnt - mean*mean;
        float sv = gg0[tid] * rsqrtf((float)var + 1e-5f);
        s0s[tid] = sv;
        t0s[tid] = bb0[tid] - (float)mean * sv;
        bsum[tid] = 0.f; bsq[tid] = 0.f;
    }
    int GRID = gridDim.x;
    int T0 = blockIdx.x;
    if (tid < 128) {
        idxb[tid] = g_idx[T0*128 + tid];
        if (T0 + GRID < 4096) idxb[128 + tid] = g_idx[(T0+GRID)*128 + tid];
        cp_async16(shaddr(hs + tid*4), g_H + (size_t)T0*512 + tid*4);
    }
    __syncthreads();
    {
        int bb = T0 >> 9;
#pragma unroll
        for (int k = 0; k < 8; k++) {
            int i = tid + k*256, col = i>>4, c4 = i&15;
            int m = idxb[col];
            cp_async16(shaddr(xs + swi4(col,c4)),
                       g_G + (((size_t)(bb<<12) + m)<<6) + (c4<<2));
        }
    }
    cp_commit();
    int p = 0, t = 0;
    for (int T = T0; T < 4096; T += GRID, t++) {
        int pbase = T*8;
        float* xsp = xs + p*8192;
        float* hsp = hs + p*512;
        cp_wait0(); __syncthreads();
        const float4* s0v = (const float4*)s0s;
        const float4* t0v = (const float4*)t0s;
#pragma unroll
        for (int k = 0; k < 8; k++) {
            int i = tid + k*256, col = i>>4, c4 = i&15;
            float4 g4 = *(float4*)(xsp + swi4(col,c4));
            float4 h4 = *(float4*)(hsp + (col>>4)*64 + (c4<<2));
            float4 sv = s0v[c4], tv = t0v[c4], v;
            v.x = fmaxf(fmaf(sv.x, g4.x+h4.x, tv.x), 0.f);
            v.y = fmaxf(fmaf(sv.y, g4.y+h4.y, tv.y), 0.f);
            v.z = fmaxf(fmaf(sv.z, g4.z+h4.z, tv.z), 0.f);
            v.w = fmaxf(fmaf(sv.w, g4.w+h4.w, tv.w), 0.f);
            *(float4*)(xsp + swi4(col,c4)) = v;
        }
        __syncthreads();
        int Tn = T + GRID;
        int nreg = 0;
        bool hasN2 = false;
        if (Tn < 4096) {
            float* xsn = xs + (p^1)*8192;
            const int* ib = idxb + ((t+1)&1)*128;
            int bb = Tn >> 9;
#pragma unroll
            for (int k = 0; k < 8; k++) {
                int i = tid + k*256, col = i>>4, c4 = i&15;
                int m = ib[col];
                cp_async16(shaddr(xsn + swi4(col,c4)),
                           g_G + (((size_t)(bb<<12) + m)<<6) + (c4<<2));
            }
            if (tid < 128) cp_async16(shaddr(hs + (p^1)*512 + tid*4),
                                      g_H + (size_t)Tn*512 + tid*4);
            cp_commit();
            int T2 = T + 2*GRID;
            if (tid < 128 && T2 < 4096) { nreg = g_idx[T2*128 + tid]; hasN2 = true; }
        }
        int ty = tid >> 5, tx = tid & 31;
        int o0 = ty * 8;
        ull acc2[8][4];
#pragma unroll
        for (int i = 0; i < 8; i++)
#pragma unroll
            for (int j = 0; j < 4; j++) acc2[i][j] = 0ull;
#pragma unroll
        for (int c4 = 0; c4 < 16; c4++) {
            ulonglong2 xv[4];
#pragma unroll
            for (int j = 0; j < 4; j++) xv[j] = *(const ulonglong2*)(xsp + swi4(tx + 32*j, c4));
#pragma unroll
            for (int ih = 0; ih < 2; ih++) {
                ulonglong2 wv[4];
#pragma unroll
                for (int i = 0; i < 4; i++) wv[i] = *(const ulonglong2*)(Ws + swi4(o0 + ih*4 + i, c4));
#pragma unroll
                for (int i = 0; i < 4; i++)
#pragma unroll
                    for (int j = 0; j < 4; j++) {
                        FMA2(acc2[ih*4+i][j], wv[i].x, xv[j].x);
                        FMA2(acc2[ih*4+i][j], wv[i].y, xv[j].y);
                    }
            }
        }
        float v[8][4];
#pragma unroll
        for (int i = 0; i < 8; i++)
#pragma unroll
            for (int j = 0; j < 4; j++) v[i][j] = lo32(acc2[i][j]) + hi32(acc2[i][j]);
#pragma unroll
        for (int j = 0; j < 4; j++) {
            int col = tx + 32*j;
            float* yp = g_y1 + (((size_t)(pbase + (col>>4))*16 + (col&15))<<6) + o0;
            *(float4*)yp       = make_float4(v[0][j], v[1][j], v[2][j], v[3][j]);
            *(float4*)(yp + 4) = make_float4(v[4][j], v[5][j], v[6][j], v[7][j]);
        }
#pragma unroll
        for (int i = 0; i < 8; i++) {
            float ps = 0.f, pq = 0.f;
#pragma unroll
            for (int j = 0; j < 4; j++) { ps += v[i][j]; pq = fmaf(v[i][j], v[i][j], pq); }
#pragma unroll
            for (int s = 16; s >= 1; s >>= 1) {
                ps += __shfl_xor_sync(0xffffffffu, ps, s);
                pq += __shfl_xor_sync(0xffffffffu, pq, s);
            }
            if (tx == 0) { bsum[o0+i] += ps; bsq[o0+i] += pq; }
        }
        if (hasN2) idxb[(t&1)*128 + tid] = nreg;
        __syncthreads();
        p ^= 1;
    }
    if (tid < 64) { atomicAdd(&g_sum1[tid], (double)bsum[tid]); atomicAdd(&g_sq1[tid], (double)bsq[tid]); }
}

// ---------------- layer2: warp-level mma.sync bf16 hi/lo split, persistent ----------------
#define BSTR 72   // bf16 per column row (stride); banks 4r+cq -> conflict-free
__global__ __launch_bounds__(256,2) void layer2_tc_kernel(const float* __restrict__ W2,
                                                          const float* __restrict__ gg1,
                                                          const float* __restrict__ bb1) {
    __shared__ __nv_bfloat16 Bhi[128*BSTR];
    __shared__ __nv_bfloat16 Blo[128*BSTR];
    __shared__ float s1s[64], t1s[64];
    int tid = threadIdx.x, wid = tid >> 5, lane = tid & 31;
    int r = lane >> 2, cq = lane & 3;
    if (tid < 64) {
        const double cnt = (double)BB*NN*KK;
        double mean = g_sum1[tid] / cnt;
        double var  = g_sq1[tid] / cnt - mean*mean;
        float sv = gg1[tid] * rsqrtf((float)var + 1e-5f);
        s1s[tid] = sv;
        t1s[tid] = bb1[tid] - (float)mean * sv;
    }
    // A fragments (W2) in registers for the whole kernel: rows m=wid*16+r(+8)
    unsigned aH[4][4], aL[4][4];
    {
        int m0 = wid*16 + r, m1 = m0 + 8;
#pragma unroll
        for (int ks = 0; ks < 4; ks++)
#pragma unroll
            for (int h = 0; h < 2; h++) {
                int k = ks*16 + cq*2 + h*8;
                float w00 = W2[m0*64 + k], w01 = W2[m0*64 + k + 1];
                float w10 = W2[m1*64 + k], w11 = W2[m1*64 + k + 1];
                aH[ks][h*2]   = pack_hi2(w00, w01);
                aH[ks][h*2+1] = pack_hi2(w10, w11);
                aL[ks][h*2]   = pack_lo2(w00, w01);
                aL[ks][h*2+1] = pack_lo2(w10, w11);
            }
    }
    __syncthreads();
    float psum0 = 0.f, psum1 = 0.f, psq0 = 0.f, psq1 = 0.f;  // rows m0, m1
    for (int T = blockIdx.x; T < 4096; T += gridDim.x) {
        const float* yb = g_y1 + (size_t)T*8192;
#pragma unroll
        for (int kk = 0; kk < 8; kk++) {
            int idx = tid + kk*256, col = idx >> 4, f = idx & 15;
            float4 y = *(const float4*)(yb + col*64 + f*4);
            float4 sv = ((const float4*)s1s)[f], tv = ((const float4*)t1s)[f];
            float x0 = fmaxf(fmaf(sv.x, y.x, tv.x), 0.f);
            float x1 = fmaxf(fmaf(sv.y, y.y, tv.y), 0.f);
            float x2 = fmaxf(fmaf(sv.z, y.z, tv.z), 0.f);
            float x3 = fmaxf(fmaf(sv.w, y.w, tv.w), 0.f);
            unsigned* ph = (unsigned*)(Bhi + col*BSTR + f*4);
            unsigned* pl = (unsigned*)(Blo + col*BSTR + f*4);
            ph[0] = pack_hi2(x0, x1); ph[1] = pack_hi2(x2, x3);
            pl[0] = pack_lo2(x0, x1); pl[1] = pack_lo2(x2, x3);
        }
        __syncthreads();
        int m0g = wid*16 + r;
#pragma unroll
        for (int p = 0; p < 8; p++) {
            float acc[2][4];
#pragma unroll
            for (int u = 0; u < 2; u++)
#pragma unroll
                for (int v = 0; v < 4; v++) acc[u][v] = 0.f;
            int colA = p*16 + r, colB = colA + 8;
#pragma unroll
            for (int ks = 0; ks < 4; ks++) {
                int ko = ks*16 + cq*2;
                unsigned bh0A = *(unsigned*)(Bhi + colA*BSTR + ko);
                unsigned bh1A = *(unsigned*)(Bhi + colA*BSTR + ko + 8);
                unsigned bh0B = *(unsigned*)(Bhi + colB*BSTR + ko);
                unsigned bh1B = *(unsigned*)(Bhi + colB*BSTR + ko + 8);
                unsigned bl0A = *(unsigned*)(Blo + colA*BSTR + ko);
                unsigned bl1A = *(unsigned*)(Blo + colA*BSTR + ko + 8);
                unsigned bl0B = *(unsigned*)(Blo + colB*BSTR + ko);
                unsigned bl1B = *(unsigned*)(Blo + colB*BSTR + ko + 8);
                mma_bf16(acc[0], aH[ks], bh0A, bh1A);
                mma_bf16(acc[1], aH[ks], bh0B, bh1B);
                mma_bf16(acc[0], aH[ks], bl0A, bl1A);
                mma_bf16(acc[1], aH[ks], bl0B, bl1B);
                mma_bf16(acc[0], aL[ks], bh0A, bh1A);
                mma_bf16(acc[1], aL[ks], bh0B, bh1B);
            }
            // row m0g: acc[.][0], acc[.][1]; row m0g+8: acc[.][2], acc[.][3]
            float mx0 = fmaxf(fmaxf(acc[0][0], acc[0][1]), fmaxf(acc[1][0], acc[1][1]));
            float mn0 = fminf(fminf(acc[0][0], acc[0][1]), fminf(acc[1][0], acc[1][1]));
            float mx1 = fmaxf(fmaxf(acc[0][2], acc[0][3]), fmaxf(acc[1][2], acc[1][3]));
            float mn1 = fminf(fminf(acc[0][2], acc[0][3]), fminf(acc[1][2], acc[1][3]));
            psum0 += acc[0][0] + acc[0][1] + acc[1][0] + acc[1][1];
            psum1 += acc[0][2] + acc[0][3] + acc[1][2] + acc[1][3];
            psq0 = fmaf(acc[0][0], acc[0][0], psq0); psq0 = fmaf(acc[0][1], acc[0][1], psq0);
            psq0 = fmaf(acc[1][0], acc[1][0], psq0); psq0 = fmaf(acc[1][1], acc[1][1], psq0);
            psq1 = fmaf(acc[0][2], acc[0][2], psq1); psq1 = fmaf(acc[0][3], acc[0][3], psq1);
            psq1 = fmaf(acc[1][2], acc[1][2], psq1); psq1 = fmaf(acc[1][3], acc[1][3], psq1);
#pragma unroll
            for (int s = 1; s <= 2; s <<= 1) {
                mx0 = fmaxf(mx0, __shfl_xor_sync(0xffffffffu, mx0, s));
                mn0 = fminf(mn0, __shfl_xor_sync(0xffffffffu, mn0, s));
                mx1 = fmaxf(mx1, __shfl_xor_sync(0xffffffffu, mx1, s));
                mn1 = fminf(mn1, __shfl_xor_sync(0xffffffffu, mn1, s));
            }
            if (cq == 0) {
                size_t pp = (size_t)(T*8 + p)*128;
                g_mx[pp + m0g] = mx0; g_mn[pp + m0g] = mn0;
                g_mx[pp + m0g + 8] = mx1; g_mn[pp + m0g + 8] = mn1;
            }
        }
        __syncthreads();
    }
#pragma unroll
    for (int s = 1; s <= 2; s <<= 1) {
        psum0 += __shfl_xor_sync(0xffffffffu, psum0, s);
        psum1 += __shfl_xor_sync(0xffffffffu, psum1, s);
        psq0  += __shfl_xor_sync(0xffffffffu, psq0, s);
        psq1  += __shfl_xor_sync(0xffffffffu, psq1, s);
    }
    if (cq == 0) {
        int m0g = wid*16 + r;
        atomicAdd(&g_sum2[m0g], (double)psum0);
        atomicAdd(&g_sq2[m0g], (double)psq0);
        atomicAdd(&g_sum2[m0g + 8], (double)psum1);
        atomicAdd(&g_sq2[m0g + 8], (double)psq1);
    }
}

__global__ void final_out_kernel(float* __restrict__ out,
                                 const float* __restrict__ gg2,
                                 const float* __restrict__ bb2) {
    __shared__ float tile[32][129];
    __shared__ float s2s[128], t2s[128];
    int tid = threadIdx.x;
    if (tid < 128) {
        const double cnt = (double)BB*NN*KK;
        double mean = g_sum2[tid] / cnt;
        double var  = g_sq2[tid] / cnt - mean*mean;
        float sv = gg2[tid] * rsqrtf((float)var + 1e-5f);
        s2s[tid] = sv;
        t2s[tid] = bb2[tid] - (float)mean * sv;
    }
    __syncthreads();
    int bn0 = blockIdx.x * 32;
    int b = bn0 >> 12, n0 = bn0 & 4095;
    for (int i = tid; i < 32*128; i += 256) {
        int r = i >> 7, o = i & 127;
        float s = s2s[o], t = t2s[o];
        size_t p = (size_t)(bn0 + r)*128 + o;
        float v = fmaxf(fmaf(s, g_mx[p], t), fmaf(s, g_mn[p], t));
        tile[r][o] = fmaxf(v, 0.f);
    }
    __syncthreads();
    for (int i = tid; i < 4096; i += 256) {
        int o = i >> 5, j = i & 31;
        out[(size_t)b*128*NN + o*NN + n0 + j] = tile[j][o];
    }
}

extern "C" void kernel_launch(void* const* d_in, const int* in_sizes, int n_in,
                              void* d_out, int out_size) {
    const float* pos1   = (const float*)d_in[0];
    const float* pos1re = (const float*)d_in[1];
    const float* pos2   = (const float*)d_in[2];
    const float* f1     = (const float*)d_in[3];
    const float* f2     = (const float*)d_in[4];
    const float* W0 = (const float*)d_in[6];
    const float* g0 = (const float*)d_in[7];
    const float* b0 = (const float*)d_in[8];
    const float* W1 = (const float*)d_in[9];
    const float* g1 = (const float*)d_in[10];
    const float* b1 = (const float*)d_in[11];
    const float* W2 = (const float*)d_in[12];
    const float* g2 = (const float*)d_in[13];
    const float* b2 = (const float*)d_in[14];

    float* out = (float*)d_out;
    const size_t featElems = (size_t)BB*128*NN;
    const size_t posElems  = (size_t)BB*3*NN;
    float* featOut = out + ((size_t)out_size - featElems);
    if ((size_t)out_size > featElems)
        cudaMemcpyAsync(out, pos1, posElems*sizeof(float), cudaMemcpyDeviceToDevice);

    static bool attrs_set = false;
    if (!attrs_set) {
        cudaFuncSetAttribute(layer1_kernel, cudaFuncAttributeMaxDynamicSharedMemorySize, 88064);
        attrs_set = true;
    }

    knn_part_kernel<<<dim3(32, 8, 2), 128>>>(pos1re, pos2);
    merge_gh_kernel<<<640, 256>>>(pos1, pos2, f1, f2, W0);
    stats0_kernel<<<2048, 256>>>();
    layer1_kernel<<<304, 256, 88064>>>(W1, g0, b0);
    layer2_tc_kernel<<<296, 256>>>(W2, g1, b1);
    final_out_kernel<<<1024, 256>>>(featOut, g2, b2);
}